// round 14
// baseline (speedup 1.0000x reference)
#include <cuda_runtime.h>
#include <math.h>
#include <stdint.h>

#define Bv 32
#define Tv 8
#define BT 256
#define Ev 128
#define Fv 512
#define NHEADv 8
#define DHv 16
#define NSPv 6
#define NUMCLSv 4
#define HFEATv 128
#define WINDOWv 4
#define NLAYERSv 2
#define L0 134
#define L1 38
#define L2 22
#define OFF1 34304          /* 256*134 */
#define OFF2 44032          /* +256*38 */
#define MTOT 49664          /* +256*22 */

// ---------------- scratch (device globals; no allocation allowed) ----------------
__device__ float g_X[MTOT*Ev];
__device__ float g_QKV[MTOT*384];
__device__ float g_Ob[MTOT*Ev];
__device__ float g_FF[MTOT*Fv];
__device__ float g_Wqkv[6*Ev*384];
__device__ float g_bqkv[6*384];
__device__ float g_mu[MTOT];
__device__ float g_rs[MTOT];

// ---------------- helpers ----------------
__device__ __forceinline__ float to_tf32(float x) {
    uint32_t u;
    asm("cvt.rna.tf32.f32 %0, %1;" : "=r"(u) : "f"(x));
    return __uint_as_float(u);
}

// ---------------- build all-scale sequences: specials + grouped mean pooling -----
__global__ void build_x_kernel(const float* __restrict__ emb,
                               const float* __restrict__ cls,
                               const float* __restrict__ glb,
                               float* __restrict__ X) {
    int idx = blockIdx.x * blockDim.x + threadIdx.x;
    if (idx >= MTOT * Ev) return;
    int e = idx & (Ev - 1);
    int r = idx >> 7;
    int L, off, g;
    if (r < OFF1)      { L = L0; off = 0;    g = 1; }
    else if (r < OFF2) { L = L1; off = OFF1; g = 4; }
    else               { L = L2; off = OFF2; g = 8; }
    int rr = r - off;
    int bt = rr / L;
    int l  = rr % L;
    float v;
    if (l < NUMCLSv) {
        v = cls[l * Ev + e];
    } else if (l < NSPv) {
        v = glb[(l - NUMCLSv) * Ev + e];
    } else {
        int k = l - NSPv;
        const float* base = emb + ((size_t)bt * (NSPv + HFEATv) + NSPv + (size_t)k * g) * Ev + e;
        float s = 0.f;
        for (int j = 0; j < g; j++) s += base[(size_t)j * Ev];
        v = s / (float)g;
    }
    X[idx] = v;
}

// ---------------- per-row LN stats: mean + rstd (warp per row, 8 rows/block) -----
__global__ void ln_stats_kernel(const float* __restrict__ X,
                                float* __restrict__ mu, float* __restrict__ rs) {
    int row = blockIdx.x * 8 + (threadIdx.x >> 5);
    int lane = threadIdx.x & 31;
    if (row >= MTOT) return;
    float4 v = *(const float4*)&X[(size_t)row * Ev + lane * 4];
    float s = v.x + v.y + v.z + v.w;
    #pragma unroll
    for (int o = 16; o > 0; o >>= 1) s += __shfl_xor_sync(0xffffffffu, s, o);
    float mean = s * (1.f / Ev);
    float d0 = v.x - mean, d1 = v.y - mean, d2 = v.z - mean, d3 = v.w - mean;
    float s2 = d0 * d0 + d1 * d1 + d2 * d2 + d3 * d3;
    #pragma unroll
    for (int o = 16; o > 0; o >>= 1) s2 += __shfl_xor_sync(0xffffffffu, s2, o);
    if (lane == 0) {
        mu[row] = mean;
        rs[row] = rsqrtf(s2 * (1.f / Ev) + 1e-5f);
    }
}

// ---------------- pack ALL 6 QKV weight/bias sets into [6][E][384] ----------------
__global__ void pack_qkv_all_kernel(const float* __restrict__ Wq, const float* __restrict__ Wk,
                                    const float* __restrict__ Wv, const float* __restrict__ bq,
                                    const float* __restrict__ bk, const float* __restrict__ bv,
                                    float* __restrict__ Wp, float* __restrict__ bp) {
    int idx = blockIdx.x * blockDim.x + threadIdx.x;
    if (idx < 6 * 384) {
        int wi = idx / 384, n = idx % 384;
        int which = n >> 7, col = n & 127;
        const float* src = (which == 0) ? bq : (which == 1) ? bk : bv;
        bp[idx] = src[wi * Ev + col];
    }
    if (idx < 6 * Ev * 384) {
        int wi = idx / (Ev * 384), r = idx % (Ev * 384);
        int k = r / 384, n = r % 384;
        int which = n >> 7, col = n & 127;
        const float* src = ((which == 0) ? Wq : (which == 1) ? Wk : Wv) + (size_t)wi * Ev * Ev;
        Wp[idx] = src[k * Ev + col];
    }
}

// ---------------- TF32 tensor-core GEMM, per-scale weights, LN fused on A --------
// Block tile 128x128, 8 warps of 64x32 (4 m16 x 4 n8, mma.m16n8k8.tf32).
// Rows are the concatenation of 3 scales; each block picks its scale's weights.
#define SA_STRIDE 20
#define SW_STRIDE 136
template<int DO_GELU, int DO_LN>
__global__ __launch_bounds__(256, 2) void gemm_tc_kernel(
        const float* __restrict__ A,
        const float* __restrict__ Wb, int wStride,
        const float* __restrict__ biasB, int bStride,
        const float* __restrict__ resid,
        const float* __restrict__ lnGb, const float* __restrict__ lnBb, int lnStride,
        const float* __restrict__ mu, const float* __restrict__ rs,
        float* __restrict__ C, int N, int K) {
    __shared__ float sA[2][128][SA_STRIDE];
    __shared__ float sW[2][16][SW_STRIDE];

    int tid = threadIdx.x;
    int lane = tid & 31, w = tid >> 5;
    int g2 = lane >> 2, c4 = lane & 3;
    int wm = w & 1, wn = w >> 1;              // warp tile: rows wm*64, cols wn*32
    int m0 = blockIdx.y * 128, n0 = blockIdx.x * 128;

    int sIdx = (m0 >= OFF2) ? 2 : ((m0 >= OFF1) ? 1 : 0);
    const float* W    = Wb    + (size_t)sIdx * wStride;
    const float* bias = biasB + (size_t)sIdx * bStride;
    const float* lnG  = DO_LN ? (lnGb + (size_t)sIdx * lnStride) : nullptr;
    const float* lnB  = DO_LN ? (lnBb + (size_t)sIdx * lnStride) : nullptr;

    // loader coords
    int ar = tid >> 1;               // A row 0..127
    int ac = (tid & 1) * 8;          // A k-offset 0 or 8
    int wr = tid >> 4;               // W k-row 0..15
    int wc = (tid & 15) * 8;         // W col

    const float* Aptr = A + (size_t)(m0 + ar) * K + ac;
    const float* Wptr = W + (size_t)wr * N + n0 + wc;

    float rowMu = 0.f, rowRs = 1.f;
    if (DO_LN) { rowMu = mu[m0 + ar]; rowRs = rs[m0 + ar]; }

    int nc = K >> 4;

    float acc[4][4][4];
    #pragma unroll
    for (int mi = 0; mi < 4; mi++)
        #pragma unroll
        for (int ni = 0; ni < 4; ni++)
            #pragma unroll
            for (int r = 0; r < 4; r++) acc[mi][ni][r] = 0.f;

    // prologue: load + stage chunk 0
    float4 aR0 = *(const float4*)Aptr;
    float4 aR1 = *(const float4*)(Aptr + 4);
    float4 wR0 = *(const float4*)Wptr;
    float4 wR1 = *(const float4*)(Wptr + 4);
    {
        float4 t0 = aR0, t1 = aR1;
        if (DO_LN) {
            float4 g0 = *(const float4*)&lnG[ac];
            float4 g1 = *(const float4*)&lnG[ac + 4];
            float4 b0 = *(const float4*)&lnB[ac];
            float4 b1 = *(const float4*)&lnB[ac + 4];
            t0.x = (t0.x - rowMu) * rowRs * g0.x + b0.x;
            t0.y = (t0.y - rowMu) * rowRs * g0.y + b0.y;
            t0.z = (t0.z - rowMu) * rowRs * g0.z + b0.z;
            t0.w = (t0.w - rowMu) * rowRs * g0.w + b0.w;
            t1.x = (t1.x - rowMu) * rowRs * g1.x + b1.x;
            t1.y = (t1.y - rowMu) * rowRs * g1.y + b1.y;
            t1.z = (t1.z - rowMu) * rowRs * g1.z + b1.z;
            t1.w = (t1.w - rowMu) * rowRs * g1.w + b1.w;
        }
        t0.x = to_tf32(t0.x); t0.y = to_tf32(t0.y); t0.z = to_tf32(t0.z); t0.w = to_tf32(t0.w);
        t1.x = to_tf32(t1.x); t1.y = to_tf32(t1.y); t1.z = to_tf32(t1.z); t1.w = to_tf32(t1.w);
        *(float4*)&sA[0][ar][ac]     = t0;
        *(float4*)&sA[0][ar][ac + 4] = t1;
        float4 u0, u1;
        u0.x = to_tf32(wR0.x); u0.y = to_tf32(wR0.y); u0.z = to_tf32(wR0.z); u0.w = to_tf32(wR0.w);
        u1.x = to_tf32(wR1.x); u1.y = to_tf32(wR1.y); u1.z = to_tf32(wR1.z); u1.w = to_tf32(wR1.w);
        *(float4*)&sW[0][wr][wc]     = u0;
        *(float4*)&sW[0][wr][wc + 4] = u1;
    }
    __syncthreads();

    for (int ch = 0; ch < nc; ch++) {
        int cur = ch & 1, nxt = cur ^ 1;
        if (ch + 1 < nc) {
            aR0 = *(const float4*)(Aptr + (ch + 1) * 16);
            aR1 = *(const float4*)(Aptr + (ch + 1) * 16 + 4);
            wR0 = *(const float4*)(Wptr + (size_t)(ch + 1) * 16 * N);
            wR1 = *(const float4*)(Wptr + (size_t)(ch + 1) * 16 * N + 4);
        }
        #pragma unroll
        for (int st = 0; st < 2; st++) {
            int k8 = st * 8;
            uint32_t af[4][4];
            #pragma unroll
            for (int mi = 0; mi < 4; mi++) {
                int r = wm * 64 + mi * 16 + g2;
                af[mi][0] = __float_as_uint(sA[cur][r][k8 + c4]);
                af[mi][1] = __float_as_uint(sA[cur][r + 8][k8 + c4]);
                af[mi][2] = __float_as_uint(sA[cur][r][k8 + c4 + 4]);
                af[mi][3] = __float_as_uint(sA[cur][r + 8][k8 + c4 + 4]);
            }
            uint32_t bf[4][2];
            #pragma unroll
            for (int ni = 0; ni < 4; ni++) {
                int col = wn * 32 + ni * 8 + g2;
                bf[ni][0] = __float_as_uint(sW[cur][k8 + c4][col]);
                bf[ni][1] = __float_as_uint(sW[cur][k8 + c4 + 4][col]);
            }
            #pragma unroll
            for (int mi = 0; mi < 4; mi++)
                #pragma unroll
                for (int ni = 0; ni < 4; ni++) {
                    asm volatile(
                        "mma.sync.aligned.m16n8k8.row.col.f32.tf32.tf32.f32 "
                        "{%0,%1,%2,%3}, {%4,%5,%6,%7}, {%8,%9}, {%0,%1,%2,%3};"
                        : "+f"(acc[mi][ni][0]), "+f"(acc[mi][ni][1]),
                          "+f"(acc[mi][ni][2]), "+f"(acc[mi][ni][3])
                        : "r"(af[mi][0]), "r"(af[mi][1]), "r"(af[mi][2]), "r"(af[mi][3]),
                          "r"(bf[ni][0]), "r"(bf[ni][1]));
                }
        }
        if (ch + 1 < nc) {
            float4 t0 = aR0, t1 = aR1;
            if (DO_LN) {
                int kb = (ch + 1) * 16;
                float4 g0 = *(const float4*)&lnG[kb + ac];
                float4 g1 = *(const float4*)&lnG[kb + ac + 4];
                float4 b0 = *(const float4*)&lnB[kb + ac];
                float4 b1 = *(const float4*)&lnB[kb + ac + 4];
                t0.x = (t0.x - rowMu) * rowRs * g0.x + b0.x;
                t0.y = (t0.y - rowMu) * rowRs * g0.y + b0.y;
                t0.z = (t0.z - rowMu) * rowRs * g0.z + b0.z;
                t0.w = (t0.w - rowMu) * rowRs * g0.w + b0.w;
                t1.x = (t1.x - rowMu) * rowRs * g1.x + b1.x;
                t1.y = (t1.y - rowMu) * rowRs * g1.y + b1.y;
                t1.z = (t1.z - rowMu) * rowRs * g1.z + b1.z;
                t1.w = (t1.w - rowMu) * rowRs * g1.w + b1.w;
            }
            t0.x = to_tf32(t0.x); t0.y = to_tf32(t0.y); t0.z = to_tf32(t0.z); t0.w = to_tf32(t0.w);
            t1.x = to_tf32(t1.x); t1.y = to_tf32(t1.y); t1.z = to_tf32(t1.z); t1.w = to_tf32(t1.w);
            *(float4*)&sA[nxt][ar][ac]     = t0;
            *(float4*)&sA[nxt][ar][ac + 4] = t1;
            float4 u0, u1;
            u0.x = to_tf32(wR0.x); u0.y = to_tf32(wR0.y); u0.z = to_tf32(wR0.z); u0.w = to_tf32(wR0.w);
            u1.x = to_tf32(wR1.x); u1.y = to_tf32(wR1.y); u1.z = to_tf32(wR1.z); u1.w = to_tf32(wR1.w);
            *(float4*)&sW[nxt][wr][wc]     = u0;
            *(float4*)&sW[nxt][wr][wc + 4] = u1;
        }
        __syncthreads();
    }

    // epilogue
    #pragma unroll
    for (int mi = 0; mi < 4; mi++) {
        #pragma unroll
        for (int ni = 0; ni < 4; ni++) {
            int col = n0 + wn * 32 + ni * 8 + 2 * c4;
            float2 bv2 = *(const float2*)&bias[col];
            #pragma unroll
            for (int half = 0; half < 2; half++) {
                int row = m0 + wm * 64 + mi * 16 + g2 + half * 8;
                float2 v;
                v.x = acc[mi][ni][half * 2 + 0] + bv2.x;
                v.y = acc[mi][ni][half * 2 + 1] + bv2.y;
                size_t ci = (size_t)row * N + col;
                if (resid) {
                    float2 r2 = *(const float2*)&resid[ci];
                    v.x += r2.x; v.y += r2.y;
                }
                if (DO_GELU) {
                    float x = v.x, cc = x + 0.044715f * x * x * x;
                    v.x = 0.5f * x * (1.f + tanhf(0.7978845608028654f * cc));
                    x = v.y; cc = x + 0.044715f * x * x * x;
                    v.y = 0.5f * x * (1.f + tanhf(0.7978845608028654f * cc));
                }
                *(float2*)&C[ci] = v;
            }
        }
    }
}

// ---------------- attention: all scales in one launch ----------------------------
// blockIdx.x: [0,2048) s0, [2048,4096) s1, [4096,6144) s2; within: bt*8 + h.
__global__ __launch_bounds__(256) void attn2_kernel(
        const float* __restrict__ QKV, float* __restrict__ O) {
    int s   = blockIdx.x >> 11;
    int rem = blockIdx.x & 2047;
    int h   = rem & 7;
    int bt  = rem >> 3;
    int L   = (s == 0) ? L0 : ((s == 1) ? L1 : L2);
    int rowbase = ((s == 0) ? 0 : ((s == 1) ? OFF1 : OFF2)) + bt * L;

    __shared__ float Ksh[L0][20];
    __shared__ float Vsh[L0][16];
    __shared__ float esh[8][L0];
    __shared__ float invs[8];
    int tid = threadIdx.x;
    int w = tid >> 5, lane = tid & 31;

    if (tid < 8) invs[tid] = powf(100000.0f, -(float)tid / 8.0f);
    __syncthreads();

    for (int i = tid; i < L * 8; i += 256) {
        int m = i >> 3, j = i & 7;
        size_t base = ((size_t)(rowbase + m)) * 384 + h * DHv + j;
        float k1 = QKV[base + 128], k2 = QKV[base + 128 + 8];
        float sv, cv;
        sincosf((float)m * invs[j], &sv, &cv);
        Ksh[m][j]     = k1 * cv - k2 * sv;
        Ksh[m][j + 8] = k1 * sv + k2 * cv;
        Vsh[m][j]     = QKV[base + 256];
        Vsh[m][j + 8] = QKV[base + 256 + 8];
    }
    __syncthreads();

    for (int lq = w; lq < L; lq += 8) {
        const float* qp = QKV + (size_t)(rowbase + lq) * 384 + h * DHv;
        float q[16];
        *(float4*)&q[0]  = *(const float4*)&qp[0];
        *(float4*)&q[4]  = *(const float4*)&qp[4];
        *(float4*)&q[8]  = *(const float4*)&qp[8];
        *(float4*)&q[12] = *(const float4*)&qp[12];
        float mys = 0.f, myc = 1.f;
        if (lane < 8) sincosf((float)lq * invs[lane], &mys, &myc);
        #pragma unroll
        for (int j = 0; j < 8; j++) {
            float cv = __shfl_sync(0xffffffffu, myc, j);
            float sv = __shfl_sync(0xffffffffu, mys, j);
            float q1 = q[j], q2 = q[j + 8];
            q[j]     = q1 * cv - q2 * sv;
            q[j + 8] = q1 * sv + q2 * cv;
        }

        if (lq >= NSPv) {
            int lo = lq - WINDOWv; if (lo < NSPv) lo = NSPv;
            int hi = lq + WINDOWv; if (hi > L - 1) hi = L - 1;
            int cnt = 6 + (hi - lo + 1);
            int m = (lane < 6) ? lane : (lo + lane - 6);
            if (m > L - 1) m = L - 1;
            bool act = lane < cnt;
            float sc = -1e30f;
            if (act) {
                float d = 0.f;
                #pragma unroll
                for (int dd = 0; dd < 16; dd++) d += q[dd] * Ksh[m][dd];
                sc = d * 0.25f;
            }
            float mx = sc;
            #pragma unroll
            for (int o = 16; o > 0; o >>= 1) mx = fmaxf(mx, __shfl_xor_sync(0xffffffffu, mx, o));
            float e = act ? expf(sc - mx) : 0.f;
            float sum = e;
            #pragma unroll
            for (int o = 16; o > 0; o >>= 1) sum += __shfl_xor_sync(0xffffffffu, sum, o);
            int d = lane & 15;
            float ov = 0.f;
            #pragma unroll
            for (int i = 0; i < 15; i++) {
                float ei = __shfl_sync(0xffffffffu, e, i);
                if (i < cnt) {
                    int mi = (i < 6) ? i : (lo + i - 6);
                    ov += ei * Vsh[mi][d];
                }
            }
            if (lane < 16)
                O[((size_t)(rowbase + lq)) * Ev + h * DHv + lane] = ov / sum;
        } else {
            float mx = -1e30f;
            for (int m = lane; m < L; m += 32) {
                float d = 0.f;
                #pragma unroll
                for (int dd = 0; dd < 16; dd++) d += q[dd] * Ksh[m][dd];
                d *= 0.25f;
                esh[w][m] = d;
                mx = fmaxf(mx, d);
            }
            #pragma unroll
            for (int o = 16; o > 0; o >>= 1) mx = fmaxf(mx, __shfl_xor_sync(0xffffffffu, mx, o));
            float sum = 0.f;
            for (int m = lane; m < L; m += 32) {
                float e = expf(esh[w][m] - mx);
                esh[w][m] = e;
                sum += e;
            }
            #pragma unroll
            for (int o = 16; o > 0; o >>= 1) sum += __shfl_xor_sync(0xffffffffu, sum, o);
            __syncwarp();
            int d = lane & 15, half = lane >> 4;
            float ov = 0.f;
            for (int m = half; m < L; m += 2) ov += esh[w][m] * Vsh[m][d];
            ov += __shfl_xor_sync(0xffffffffu, ov, 16);
            if (lane < 16)
                O[((size_t)(rowbase + lq)) * Ev + h * DHv + lane] = ov / sum;
            __syncwarp();
        }
    }
}

// ---------------- CLS gather (3 scales) + mean + final LN + write -----------------
__global__ void cls_final_kernel(const float* __restrict__ X,
                                 const float* __restrict__ og, const float* __restrict__ ob,
                                 float* __restrict__ out) {
    int row = blockIdx.x;        // bt*4 + c
    int bt = row >> 2, c = row & 3;
    int t = threadIdx.x;
    float v = (X[((size_t)(bt * L0 + c)) * Ev + t]
             + X[((size_t)(OFF1 + bt * L1 + c)) * Ev + t]
             + X[((size_t)(OFF2 + bt * L2 + c)) * Ev + t]) * (1.f / 3.f);
    __shared__ float sh[4];
    float s = v;
    #pragma unroll
    for (int o = 16; o > 0; o >>= 1) s += __shfl_xor_sync(0xffffffffu, s, o);
    if ((t & 31) == 0) sh[t >> 5] = s;
    __syncthreads();
    float mean = (sh[0] + sh[1] + sh[2] + sh[3]) * (1.f / Ev);
    float d = v - mean;
    float s2 = d * d;
    #pragma unroll
    for (int o = 16; o > 0; o >>= 1) s2 += __shfl_xor_sync(0xffffffffu, s2, o);
    __syncthreads();
    if ((t & 31) == 0) sh[t >> 5] = s2;
    __syncthreads();
    float var = (sh[0] + sh[1] + sh[2] + sh[3]) * (1.f / Ev);
    out[(size_t)row * Ev + t] = d * rsqrtf(var + 1e-5f) * og[t] + ob[t];
}

// ---------------- host orchestration ----------------
extern "C" void kernel_launch(void* const* d_in, const int* in_sizes, int n_in,
                              void* d_out, int out_size) {
    const float* emb   = (const float*)d_in[0];
    const float* cls   = (const float*)d_in[1];
    const float* glb   = (const float*)d_in[2];
    const float* Wq    = (const float*)d_in[3];
    const float* bq    = (const float*)d_in[4];
    const float* Wk    = (const float*)d_in[5];
    const float* bk    = (const float*)d_in[6];
    const float* Wv    = (const float*)d_in[7];
    const float* bv    = (const float*)d_in[8];
    const float* Wo    = (const float*)d_in[9];
    const float* bo    = (const float*)d_in[10];
    const float* ln1g  = (const float*)d_in[11];
    const float* ln1b  = (const float*)d_in[12];
    const float* ln2g  = (const float*)d_in[13];
    const float* ln2b  = (const float*)d_in[14];
    const float* W1    = (const float*)d_in[15];
    const float* b1    = (const float*)d_in[16];
    const float* W2    = (const float*)d_in[17];
    const float* b2    = (const float*)d_in[18];
    const float* outg  = (const float*)d_in[19];
    const float* outb  = (const float*)d_in[20];
    float* out = (float*)d_out;

    float *X, *QKV, *Ob, *FF, *Wp, *bp, *mu, *rs;
    cudaGetSymbolAddress((void**)&X,    g_X);
    cudaGetSymbolAddress((void**)&QKV,  g_QKV);
    cudaGetSymbolAddress((void**)&Ob,   g_Ob);
    cudaGetSymbolAddress((void**)&FF,   g_FF);
    cudaGetSymbolAddress((void**)&Wp,   g_Wqkv);
    cudaGetSymbolAddress((void**)&bp,   g_bqkv);
    cudaGetSymbolAddress((void**)&mu,   g_mu);
    cudaGetSymbolAddress((void**)&rs,   g_rs);

    // pack all 6 (scale, layer) QKV weight sets once
    pack_qkv_all_kernel<<<(6 * Ev * 384 + 255) / 256, 256>>>(Wq, Wk, Wv, bq, bk, bv, Wp, bp);

    // build all 3 scales' sequences
    build_x_kernel<<<(MTOT * Ev + 255) / 256, 256>>>(emb, cls, glb, X);

    const int GY = MTOT / 128;   // 388

    for (int l = 0; l < NLAYERSv; l++) {
        // LN1 stats + fused QKV gemm (per-scale weights resolved in-kernel)
        ln_stats_kernel<<<MTOT / 8, 256>>>(X, mu, rs);
        {
            dim3 gr(384 / 128, GY);
            gemm_tc_kernel<0, 1><<<gr, 256>>>(
                X, Wp + (size_t)l * Ev * 384, NLAYERSv * Ev * 384,
                bp + l * 384, NLAYERSv * 384,
                nullptr,
                ln1g + (size_t)l * Ev, ln1b + (size_t)l * Ev, NLAYERSv * Ev,
                mu, rs, QKV, 384, Ev);
        }

        attn2_kernel<<<3 * BT * NHEADv, 256>>>(QKV, Ob);

        // O-proj + residual -> X
        {
            dim3 gr(1, GY);
            gemm_tc_kernel<0, 0><<<gr, 256>>>(
                Ob, Wo + (size_t)l * Ev * Ev, NLAYERSv * Ev * Ev,
                bo + l * Ev, NLAYERSv * Ev,
                X, nullptr, nullptr, 0, nullptr, nullptr, X, Ev, Ev);
        }

        // LN2 stats + fused FF1 gemm (+GELU)
        ln_stats_kernel<<<MTOT / 8, 256>>>(X, mu, rs);
        {
            dim3 gr(Fv / 128, GY);
            gemm_tc_kernel<1, 1><<<gr, 256>>>(
                X, W1 + (size_t)l * Ev * Fv, NLAYERSv * Ev * Fv,
                b1 + l * Fv, NLAYERSv * Fv,
                nullptr,
                ln2g + (size_t)l * Ev, ln2b + (size_t)l * Ev, NLAYERSv * Ev,
                mu, rs, FF, Fv, Ev);
        }
        // FF2 + residual -> X
        {
            dim3 gr(1, GY);
            gemm_tc_kernel<0, 0><<<gr, 256>>>(
                FF, W2 + (size_t)l * Fv * Ev, NLAYERSv * Fv * Ev,
                b2 + l * Ev, NLAYERSv * Ev,
                X, nullptr, nullptr, 0, nullptr, nullptr, X, Ev, Fv);
        }
    }

    cls_final_kernel<<<BT * NUMCLSv, 128>>>(X, outg, outb, out);
}